// round 3
// baseline (speedup 1.0000x reference)
#include <cuda_runtime.h>

#define Himg 512
#define Wimg 512
#define HW   (Himg * Wimg)          // 262144 = 2^18
#define Bb   8
#define Cc   19
#define NPIX (Bb * HW)              // 2097152
#define NBLK 296
#define NTHR 256
#define NACC 41                      // 19 denomP + 19 inter + focal + ce + boundary

// Scratch (no allocations allowed -> __device__ globals)
__device__ unsigned char g_diff[(Himg - 2) * Wimg];
__device__ float         g_wmap[HW];
__device__ float         g_partials[NBLK * NACC];
__device__ int           g_hist[Cc];
__device__ unsigned int  g_count;

// ---------------------------------------------------------------------------
// Boundary phase 1 (int4): per (row-window i, 4 cols), any batch with the 3
// vertically adjacent targets not all equal? Also zeroes g_hist for this run.
// ---------------------------------------------------------------------------
__global__ void diff_kernel(const int* __restrict__ tgt) {
    int idx = blockIdx.x * blockDim.x + threadIdx.x;
    if (blockIdx.x == 0 && threadIdx.x < Cc) g_hist[threadIdx.x] = 0;
    if (idx >= (Himg - 2) * (Wimg / 4)) return;
    int i  = idx / (Wimg / 4);
    int w4 = idx - i * (Wimg / 4);
    int d0 = 0, d1 = 0, d2 = 0, d3 = 0;
#pragma unroll
    for (int b = 0; b < Bb; b++) {
        const int4* tp = (const int4*)(tgt + b * HW + i * Wimg) + w4;
        int4 a = tp[0];
        int4 e = tp[Wimg / 4];
        int4 c = tp[2 * (Wimg / 4)];
        d0 |= (a.x != e.x) | (e.x != c.x);
        d1 |= (a.y != e.y) | (e.y != c.y);
        d2 |= (a.z != e.z) | (e.z != c.z);
        d3 |= (a.w != e.w) | (e.w != c.w);
    }
    uchar4 r;
    r.x = (unsigned char)d0; r.y = (unsigned char)d1;
    r.z = (unsigned char)d2; r.w = (unsigned char)d3;
    ((uchar4*)g_diff)[idx] = r;
}

// ---------------------------------------------------------------------------
// Target histogram (deterministic: integer atomics).
// ---------------------------------------------------------------------------
__global__ void histo_kernel(const int* __restrict__ tgt) {
    __shared__ int h[Cc];
    if (threadIdx.x < Cc) h[threadIdx.x] = 0;
    __syncthreads();
    int stride = gridDim.x * blockDim.x;
    for (int q = blockIdx.x * blockDim.x + threadIdx.x; q < NPIX / 4; q += stride) {
        int4 t = ((const int4*)tgt)[q];
        atomicAdd(&h[t.x], 1);
        atomicAdd(&h[t.y], 1);
        atomicAdd(&h[t.z], 1);
        atomicAdd(&h[t.w], 1);
    }
    __syncthreads();
    if (threadIdx.x < Cc) atomicAdd(&g_hist[threadIdx.x], h[threadIdx.x]);
}

// ---------------------------------------------------------------------------
// Boundary phase 2: OR over 3 adjacent columns -> weight map 1 + 0.5*bmap.
// Also resets the last-block ticket for the fused final reduction.
// ---------------------------------------------------------------------------
__global__ void wmap_kernel() {
    int idx = blockIdx.x * blockDim.x + threadIdx.x;
    if (idx == 0) g_count = 0;
    if (idx >= HW) return;
    int h = idx >> 9;
    int w = idx & (Wimg - 1);
    float v = 1.0f;
    if (h >= 1 && h <= Himg - 2 && w >= 1 && w <= Wimg - 2) {
        int i = h - 1, j = w - 1;
        int d = g_diff[i * Wimg + j] | g_diff[i * Wimg + j + 1] | g_diff[i * Wimg + j + 2];
        if (d) v = 1.5f;
    }
    g_wmap[idx] = v;
}

// ---------------------------------------------------------------------------
// Main streaming reduction (scalar coalesced loads, occ 2) + fused final
// reduction in the last block to finish (deterministic: reduce order fixed).
// ---------------------------------------------------------------------------
__global__ void __launch_bounds__(NTHR, 2)
main_kernel(const float* __restrict__ in, const int* __restrict__ tgt,
            float* __restrict__ out) {
    float denom[Cc], inter[Cc];
#pragma unroll
    for (int c = 0; c < Cc; c++) { denom[c] = 0.0f; inter[c] = 0.0f; }
    float facc = 0.0f, ceacc = 0.0f, bacc = 0.0f;

    const float L2E = 1.44269504088896f;
    const int stride = gridDim.x * blockDim.x;
    for (int p = blockIdx.x * blockDim.x + threadIdx.x; p < NPIX; p += stride) {
        int hw = p & (HW - 1);
        int b  = p >> 18;
        const float* base = in + (size_t)(b * Cc) * HW + hw;

        float x[Cc];
#pragma unroll
        for (int c = 0; c < Cc; c++) x[c] = __ldcs(base + (size_t)c * HW);

        int   t   = tgt[p];
        float wgt = g_wmap[hw];

        float m = x[0];
#pragma unroll
        for (int c = 1; c < Cc; c++) m = fmaxf(m, x[c]);
        float nmL2 = -m * L2E;

        float s = 0.0f, sumx = 0.0f, xt = 0.0f;
#pragma unroll
        for (int c = 0; c < Cc; c++) {
            sumx += x[c];
            xt = (t == c) ? x[c] : xt;
            float e = exp2f(fmaf(x[c], L2E, nmL2));
            s += e;
            x[c] = e;                 // reuse register: exp(x - m)
        }
        float inv_s = __fdividef(1.0f, s);
        float logZ  = m + __logf(s);
        float nll   = logZ - xt;
        float pt    = exp2f(fmaf(xt, L2E, nmL2)) * inv_s;

#pragma unroll
        for (int c = 0; c < Cc; c++) {
            denom[c] = fmaf(x[c], inv_s, denom[c]);   // prob-sum only (counts via g_hist)
            if (t == c) inter[c] += pt;
        }

        float om = 1.0f - pt;
        facc  = fmaf(om * om, nll, facc);
        ceacc += 0.9f * nll + 0.1f * (logZ - sumx * (1.0f / Cc));
        bacc  = fmaf(nll, wgt, bacc);
    }

    // ---- deterministic block reduction: warp shuffles -> fixed-order smem ----
    __shared__ float sm[NTHR / 32][NACC];
    int wid  = threadIdx.x >> 5;
    int lane = threadIdx.x & 31;

#pragma unroll
    for (int c = 0; c < Cc; c++) {
        float v = denom[c];
#pragma unroll
        for (int o = 16; o > 0; o >>= 1) v += __shfl_xor_sync(0xffffffffu, v, o);
        denom[c] = v;
        float u = inter[c];
#pragma unroll
        for (int o = 16; o > 0; o >>= 1) u += __shfl_xor_sync(0xffffffffu, u, o);
        inter[c] = u;
    }
#pragma unroll
    for (int o = 16; o > 0; o >>= 1) facc  += __shfl_xor_sync(0xffffffffu, facc, o);
#pragma unroll
    for (int o = 16; o > 0; o >>= 1) ceacc += __shfl_xor_sync(0xffffffffu, ceacc, o);
#pragma unroll
    for (int o = 16; o > 0; o >>= 1) bacc  += __shfl_xor_sync(0xffffffffu, bacc, o);

    if (lane == 0) {
#pragma unroll
        for (int c = 0; c < Cc; c++) {
            sm[wid][c]      = denom[c];
            sm[wid][19 + c] = inter[c];
        }
        sm[wid][38] = facc;
        sm[wid][39] = ceacc;
        sm[wid][40] = bacc;
    }
    __syncthreads();
    if (threadIdx.x < NACC) {
        float s = 0.0f;
#pragma unroll
        for (int w = 0; w < NTHR / 32; w++) s += sm[w][threadIdx.x];
        g_partials[blockIdx.x * NACC + threadIdx.x] = s;
    }

    // ---- last-block-done ticket -> fused final reduction ----
    __shared__ bool is_last;
    __threadfence();
    __syncthreads();
    if (threadIdx.x == 0) {
        unsigned int r = atomicAdd(&g_count, 1u);
        is_last = (r == (unsigned int)(gridDim.x - 1));
    }
    __syncthreads();
    if (!is_last) return;

    __shared__ double tot[NACC];
    if (threadIdx.x < NACC) {
        const float* pp = g_partials + threadIdx.x;
        // 4 independent chains for MLP; fixed combine order -> deterministic
        double s0 = 0.0, s1 = 0.0, s2 = 0.0, s3 = 0.0;
#pragma unroll 4
        for (int b = 0; b < NBLK; b += 4) {
            s0 += (double)__ldcg(pp + (b + 0) * NACC);
            s1 += (double)__ldcg(pp + (b + 1) * NACC);
            s2 += (double)__ldcg(pp + (b + 2) * NACC);
            s3 += (double)__ldcg(pp + (b + 3) * NACC);
        }
        tot[threadIdx.x] = ((s0 + s1) + (s2 + s3));
    }
    __syncthreads();
    if (threadIdx.x == 0) {
        const double inv = 1.0 / (double)NPIX;
        double focal = tot[38] * inv;
        double ce    = tot[39] * inv;
        double bnd   = tot[40] * inv;
        double dice  = 0.0;
        for (int c = 0; c < Cc; c++) {
            double den = tot[c] + (double)g_hist[c];
            dice += 1.0 - (2.0 * tot[19 + c] + 1e-5) / (den + 1e-5);
        }
        dice /= (double)Cc;
        out[0] = (float)focal;
        out[1] = (float)dice;
        out[2] = (float)ce;
        out[3] = (float)bnd;
        out[4] = (float)(focal + dice + ce + bnd);
    }
}

extern "C" void kernel_launch(void* const* d_in, const int* in_sizes, int n_in,
                              void* d_out, int out_size) {
    const float* in  = (const float*)d_in[0];  // [8,19,512,512] f32
    const int*   tgt = (const int*)d_in[1];    // [8,512,512] i32
    float*       out = (float*)d_out;          // [5] f32

    diff_kernel<<<((Himg - 2) * (Wimg / 4) + 255) / 256, 256>>>(tgt);
    histo_kernel<<<148, 256>>>(tgt);
    wmap_kernel<<<HW / 256, 256>>>();
    main_kernel<<<NBLK, NTHR>>>(in, tgt, out);
}

// round 4
// speedup vs baseline: 1.2807x; 1.2807x over previous
#include <cuda_runtime.h>

#define Himg 512
#define Wimg 512
#define HW   (Himg * Wimg)          // 262144 = 2^18
#define Bb   8
#define Cc   19
#define NPIX (Bb * HW)              // 2097152
#define NBLK 304
#define NTHR 256
#define NACC 41                      // 19 denom + 19 inter + focal + ce + boundary
#define NCHUNK 8
#define CHUNKB (NBLK / NCHUNK)       // 38

// Scratch (no allocations allowed -> __device__ globals)
__device__ unsigned char g_diff[(Himg - 2) * Wimg];
__device__ float         g_wmap[HW];
__device__ float         g_partials[NBLK * NACC];

// ---------------------------------------------------------------------------
// Boundary phase 1 (int4): per (row-window i, 4 cols), any batch with the 3
// vertically adjacent targets not all equal?
// ---------------------------------------------------------------------------
__global__ void diff_kernel(const int* __restrict__ tgt) {
    int idx = blockIdx.x * blockDim.x + threadIdx.x;
    if (idx >= (Himg - 2) * (Wimg / 4)) return;
    int i  = idx / (Wimg / 4);
    int w4 = idx - i * (Wimg / 4);
    int d0 = 0, d1 = 0, d2 = 0, d3 = 0;
#pragma unroll
    for (int b = 0; b < Bb; b++) {
        const int4* tp = (const int4*)(tgt + b * HW + i * Wimg) + w4;
        int4 a = tp[0];
        int4 e = tp[Wimg / 4];
        int4 c = tp[2 * (Wimg / 4)];
        d0 |= (a.x != e.x) | (e.x != c.x);
        d1 |= (a.y != e.y) | (e.y != c.y);
        d2 |= (a.z != e.z) | (e.z != c.z);
        d3 |= (a.w != e.w) | (e.w != c.w);
    }
    uchar4 r;
    r.x = (unsigned char)d0; r.y = (unsigned char)d1;
    r.z = (unsigned char)d2; r.w = (unsigned char)d3;
    ((uchar4*)g_diff)[idx] = r;
}

// ---------------------------------------------------------------------------
// Boundary phase 2: OR over 3 adjacent columns -> weight map 1 + 0.5*bmap
// ---------------------------------------------------------------------------
__global__ void wmap_kernel() {
    int idx = blockIdx.x * blockDim.x + threadIdx.x;
    if (idx >= HW) return;
    int h = idx >> 9;
    int w = idx & (Wimg - 1);
    float v = 1.0f;
    if (h >= 1 && h <= Himg - 2 && w >= 1 && w <= Wimg - 2) {
        int i = h - 1, j = w - 1;
        int d = g_diff[i * Wimg + j] | g_diff[i * Wimg + j + 1] | g_diff[i * Wimg + j + 2];
        if (d) v = 1.5f;
    }
    g_wmap[idx] = v;
}

// ---------------------------------------------------------------------------
// Main streaming reduction (R1 body: this is the empirically-fast version).
// ---------------------------------------------------------------------------
__global__ void __launch_bounds__(NTHR, 2)
main_kernel(const float* __restrict__ in, const int* __restrict__ tgt) {
    float denom[Cc], inter[Cc];
#pragma unroll
    for (int c = 0; c < Cc; c++) { denom[c] = 0.0f; inter[c] = 0.0f; }
    float facc = 0.0f, ceacc = 0.0f, bacc = 0.0f;

    const int stride = gridDim.x * blockDim.x;
    for (int p = blockIdx.x * blockDim.x + threadIdx.x; p < NPIX; p += stride) {
        int hw = p & (HW - 1);
        int b  = p >> 18;
        const float* base = in + (size_t)(b * Cc) * HW + hw;

        float x[Cc];
#pragma unroll
        for (int c = 0; c < Cc; c++) x[c] = __ldcs(base + (size_t)c * HW);

        int   t   = tgt[p];
        float wgt = g_wmap[hw];

        float m = x[0];
#pragma unroll
        for (int c = 1; c < Cc; c++) m = fmaxf(m, x[c]);

        float s = 0.0f, sumx = 0.0f, xt = 0.0f;
#pragma unroll
        for (int c = 0; c < Cc; c++) {
            float f = (t == c) ? 1.0f : 0.0f;
            sumx += x[c];
            xt = fmaf(f, x[c], xt);
            float e = __expf(x[c] - m);
            s += e;
            x[c] = e;                  // reuse register for exp(x - m)
        }
        float inv_s = __fdividef(1.0f, s);
        float logZ  = m + __logf(s);
        float nll   = logZ - xt;

        float pt = 0.0f;
#pragma unroll
        for (int c = 0; c < Cc; c++) {
            float f  = (t == c) ? 1.0f : 0.0f;
            float pr = x[c] * inv_s;
            denom[c] += pr + f;                 // prob-sum + one-hot count
            inter[c] = fmaf(f, pr, inter[c]);
            pt       = fmaf(f, pr, pt);
        }

        float om = 1.0f - pt;
        facc  = fmaf(om * om, nll, facc);
        ceacc += 0.9f * nll + 0.1f * (logZ - sumx * (1.0f / Cc));
        bacc  = fmaf(nll, wgt, bacc);
    }

    // ---- deterministic block reduction: warp shuffles -> fixed-order smem ----
    __shared__ float sm[NTHR / 32][NACC];
    int wid  = threadIdx.x >> 5;
    int lane = threadIdx.x & 31;

#pragma unroll
    for (int c = 0; c < Cc; c++) {
        float v = denom[c];
#pragma unroll
        for (int o = 16; o > 0; o >>= 1) v += __shfl_xor_sync(0xffffffffu, v, o);
        denom[c] = v;
        float u = inter[c];
#pragma unroll
        for (int o = 16; o > 0; o >>= 1) u += __shfl_xor_sync(0xffffffffu, u, o);
        inter[c] = u;
    }
#pragma unroll
    for (int o = 16; o > 0; o >>= 1) facc  += __shfl_xor_sync(0xffffffffu, facc, o);
#pragma unroll
    for (int o = 16; o > 0; o >>= 1) ceacc += __shfl_xor_sync(0xffffffffu, ceacc, o);
#pragma unroll
    for (int o = 16; o > 0; o >>= 1) bacc  += __shfl_xor_sync(0xffffffffu, bacc, o);

    if (lane == 0) {
#pragma unroll
        for (int c = 0; c < Cc; c++) {
            sm[wid][c]      = denom[c];
            sm[wid][19 + c] = inter[c];
        }
        sm[wid][38] = facc;
        sm[wid][39] = ceacc;
        sm[wid][40] = bacc;
    }
    __syncthreads();
    if (threadIdx.x < NACC) {
        float s = 0.0f;
#pragma unroll
        for (int w = 0; w < NTHR / 32; w++) s += sm[w][threadIdx.x];
        g_partials[blockIdx.x * NACC + threadIdx.x] = s;
    }
}

// ---------------------------------------------------------------------------
// Final: parallel deterministic reduction. 328 threads = 41 cols x 8 chunks;
// each thread sums 38 partials (short chain), then fixed-order chunk combine.
// ---------------------------------------------------------------------------
__global__ void final_kernel(float* __restrict__ out) {
    __shared__ double ch[NCHUNK][NACC];
    __shared__ double tot[NACC];
    int tid = threadIdx.x;
    if (tid < NACC * NCHUNK) {
        int col   = tid % NACC;
        int chunk = tid / NACC;
        const float* pp = g_partials + col;
        double s = 0.0;
#pragma unroll
        for (int b = 0; b < CHUNKB; b++)
            s += (double)__ldcg(pp + (chunk * CHUNKB + b) * NACC);
        ch[chunk][col] = s;
    }
    __syncthreads();
    if (tid < NACC) {
        double s = 0.0;
#pragma unroll
        for (int k = 0; k < NCHUNK; k++) s += ch[k][tid];
        tot[tid] = s;
    }
    __syncthreads();
    if (tid == 0) {
        const double inv = 1.0 / (double)NPIX;
        double focal = tot[38] * inv;
        double ce    = tot[39] * inv;
        double bnd   = tot[40] * inv;
        double dice  = 0.0;
        for (int c = 0; c < Cc; c++) {
            dice += 1.0 - (2.0 * tot[19 + c] + 1e-5) / (tot[c] + 1e-5);
        }
        dice /= (double)Cc;
        out[0] = (float)focal;
        out[1] = (float)dice;
        out[2] = (float)ce;
        out[3] = (float)bnd;
        out[4] = (float)(focal + dice + ce + bnd);
    }
}

extern "C" void kernel_launch(void* const* d_in, const int* in_sizes, int n_in,
                              void* d_out, int out_size) {
    const float* in  = (const float*)d_in[0];  // [8,19,512,512] f32
    const int*   tgt = (const int*)d_in[1];    // [8,512,512] i32
    float*       out = (float*)d_out;          // [5] f32

    diff_kernel<<<((Himg - 2) * (Wimg / 4) + 255) / 256, 256>>>(tgt);
    wmap_kernel<<<HW / 256, 256>>>();
    main_kernel<<<NBLK, NTHR>>>(in, tgt);
    final_kernel<<<1, 352>>>(out);
}

// round 5
// speedup vs baseline: 1.3584x; 1.0607x over previous
#include <cuda_runtime.h>

#define Himg 512
#define Wimg 512
#define HW   (Himg * Wimg)          // 262144 = 2^18
#define Bb   8
#define Cc   19
#define NPIX (Bb * HW)              // 2097152
#define NBLK 304
#define NTHR 256
#define NACC 41                      // 19 denom + 19 inter + focal + ce + boundary
#define NCHUNK 6
#define CHUNKB 51                    // ceil(304/6); last chunk has 49

// Scratch (no allocations allowed -> __device__ globals)
__device__ unsigned char g_diff[(Himg - 2) * Wimg];
__device__ float         g_wmap[HW];
__device__ float         g_partials[NBLK * NACC];
__device__ unsigned int  g_count;

// ---------------------------------------------------------------------------
// Boundary phase 1 (int4): per (row-window i, 4 cols), any batch with the 3
// vertically adjacent targets not all equal?
// ---------------------------------------------------------------------------
__global__ void diff_kernel(const int* __restrict__ tgt) {
    int idx = blockIdx.x * blockDim.x + threadIdx.x;
    if (idx >= (Himg - 2) * (Wimg / 4)) return;
    int i  = idx / (Wimg / 4);
    int w4 = idx - i * (Wimg / 4);
    int d0 = 0, d1 = 0, d2 = 0, d3 = 0;
#pragma unroll
    for (int b = 0; b < Bb; b++) {
        const int4* tp = (const int4*)(tgt + b * HW + i * Wimg) + w4;
        int4 a = tp[0];
        int4 e = tp[Wimg / 4];
        int4 c = tp[2 * (Wimg / 4)];
        d0 |= (a.x != e.x) | (e.x != c.x);
        d1 |= (a.y != e.y) | (e.y != c.y);
        d2 |= (a.z != e.z) | (e.z != c.z);
        d3 |= (a.w != e.w) | (e.w != c.w);
    }
    uchar4 r;
    r.x = (unsigned char)d0; r.y = (unsigned char)d1;
    r.z = (unsigned char)d2; r.w = (unsigned char)d3;
    ((uchar4*)g_diff)[idx] = r;
}

// ---------------------------------------------------------------------------
// Boundary phase 2: OR over 3 adjacent columns -> weight map 1 + 0.5*bmap.
// Also resets the last-block ticket for the fused final reduction.
// ---------------------------------------------------------------------------
__global__ void wmap_kernel() {
    int idx = blockIdx.x * blockDim.x + threadIdx.x;
    if (idx == 0) g_count = 0;
    if (idx >= HW) return;
    int h = idx >> 9;
    int w = idx & (Wimg - 1);
    float v = 1.0f;
    if (h >= 1 && h <= Himg - 2 && w >= 1 && w <= Wimg - 2) {
        int i = h - 1, j = w - 1;
        int d = g_diff[i * Wimg + j] | g_diff[i * Wimg + j + 1] | g_diff[i * Wimg + j + 2];
        if (d) v = 1.5f;
    }
    g_wmap[idx] = v;
}

// ---------------------------------------------------------------------------
// Main streaming reduction (R1/R4 body, untouched) + fused last-block final
// reduction (deterministic: reduce order fixed, only executor identity varies).
// ---------------------------------------------------------------------------
__global__ void __launch_bounds__(NTHR, 2)
main_kernel(const float* __restrict__ in, const int* __restrict__ tgt,
            float* __restrict__ out) {
    float denom[Cc], inter[Cc];
#pragma unroll
    for (int c = 0; c < Cc; c++) { denom[c] = 0.0f; inter[c] = 0.0f; }
    float facc = 0.0f, ceacc = 0.0f, bacc = 0.0f;

    const int stride = gridDim.x * blockDim.x;
    for (int p = blockIdx.x * blockDim.x + threadIdx.x; p < NPIX; p += stride) {
        int hw = p & (HW - 1);
        int b  = p >> 18;
        const float* base = in + (size_t)(b * Cc) * HW + hw;

        float x[Cc];
#pragma unroll
        for (int c = 0; c < Cc; c++) x[c] = __ldcs(base + (size_t)c * HW);

        int   t   = tgt[p];
        float wgt = g_wmap[hw];

        float m = x[0];
#pragma unroll
        for (int c = 1; c < Cc; c++) m = fmaxf(m, x[c]);

        float s = 0.0f, sumx = 0.0f, xt = 0.0f;
#pragma unroll
        for (int c = 0; c < Cc; c++) {
            float f = (t == c) ? 1.0f : 0.0f;
            sumx += x[c];
            xt = fmaf(f, x[c], xt);
            float e = __expf(x[c] - m);
            s += e;
            x[c] = e;                  // reuse register for exp(x - m)
        }
        float inv_s = __fdividef(1.0f, s);
        float logZ  = m + __logf(s);
        float nll   = logZ - xt;

        float pt = 0.0f;
#pragma unroll
        for (int c = 0; c < Cc; c++) {
            float f  = (t == c) ? 1.0f : 0.0f;
            float pr = x[c] * inv_s;
            denom[c] += pr + f;                 // prob-sum + one-hot count
            inter[c] = fmaf(f, pr, inter[c]);
            pt       = fmaf(f, pr, pt);
        }

        float om = 1.0f - pt;
        facc  = fmaf(om * om, nll, facc);
        ceacc += 0.9f * nll + 0.1f * (logZ - sumx * (1.0f / Cc));
        bacc  = fmaf(nll, wgt, bacc);
    }

    // ---- deterministic block reduction: warp shuffles -> fixed-order smem ----
    __shared__ float sm[NTHR / 32][NACC];
    int wid  = threadIdx.x >> 5;
    int lane = threadIdx.x & 31;

#pragma unroll
    for (int c = 0; c < Cc; c++) {
        float v = denom[c];
#pragma unroll
        for (int o = 16; o > 0; o >>= 1) v += __shfl_xor_sync(0xffffffffu, v, o);
        denom[c] = v;
        float u = inter[c];
#pragma unroll
        for (int o = 16; o > 0; o >>= 1) u += __shfl_xor_sync(0xffffffffu, u, o);
        inter[c] = u;
    }
#pragma unroll
    for (int o = 16; o > 0; o >>= 1) facc  += __shfl_xor_sync(0xffffffffu, facc, o);
#pragma unroll
    for (int o = 16; o > 0; o >>= 1) ceacc += __shfl_xor_sync(0xffffffffu, ceacc, o);
#pragma unroll
    for (int o = 16; o > 0; o >>= 1) bacc  += __shfl_xor_sync(0xffffffffu, bacc, o);

    if (lane == 0) {
#pragma unroll
        for (int c = 0; c < Cc; c++) {
            sm[wid][c]      = denom[c];
            sm[wid][19 + c] = inter[c];
        }
        sm[wid][38] = facc;
        sm[wid][39] = ceacc;
        sm[wid][40] = bacc;
    }
    __syncthreads();
    if (threadIdx.x < NACC) {
        float s = 0.0f;
#pragma unroll
        for (int w = 0; w < NTHR / 32; w++) s += sm[w][threadIdx.x];
        g_partials[blockIdx.x * NACC + threadIdx.x] = s;
    }

    // ---- last-block-done ticket -> fused final reduction ----
    __shared__ bool is_last;
    __threadfence();
    __syncthreads();
    if (threadIdx.x == 0) {
        unsigned int r = atomicAdd(&g_count, 1u);
        is_last = (r == (unsigned int)(gridDim.x - 1));
    }
    __syncthreads();
    if (!is_last) return;

    // 246 threads = 41 cols x 6 chunks; each sums <=51 partials (float chain),
    // then cols combine the 6 chunk sums in double, fixed order.
    __shared__ float  ch[NCHUNK][NACC];
    __shared__ double tot[NACC];
    int tid = threadIdx.x;
    if (tid < NACC * NCHUNK) {
        int col   = tid % NACC;
        int chunk = tid / NACC;
        int b0 = chunk * CHUNKB;
        int b1 = (b0 + CHUNKB < NBLK) ? b0 + CHUNKB : NBLK;
        const float* pp = g_partials + col;
        float s = 0.0f;
        for (int b = b0; b < b1; b++) s += __ldcg(pp + b * NACC);
        ch[chunk][col] = s;
    }
    __syncthreads();
    if (tid < NACC) {
        double s = 0.0;
#pragma unroll
        for (int k = 0; k < NCHUNK; k++) s += (double)ch[k][tid];
        tot[tid] = s;
    }
    __syncthreads();
    if (tid == 0) {
        const double inv = 1.0 / (double)NPIX;
        double focal = tot[38] * inv;
        double ce    = tot[39] * inv;
        double bnd   = tot[40] * inv;
        double dice  = 0.0;
        for (int c = 0; c < Cc; c++) {
            dice += 1.0 - (2.0 * tot[19 + c] + 1e-5) / (tot[c] + 1e-5);
        }
        dice /= (double)Cc;
        out[0] = (float)focal;
        out[1] = (float)dice;
        out[2] = (float)ce;
        out[3] = (float)bnd;
        out[4] = (float)(focal + dice + ce + bnd);
    }
}

extern "C" void kernel_launch(void* const* d_in, const int* in_sizes, int n_in,
                              void* d_out, int out_size) {
    const float* in  = (const float*)d_in[0];  // [8,19,512,512] f32
    const int*   tgt = (const int*)d_in[1];    // [8,512,512] i32
    float*       out = (float*)d_out;          // [5] f32

    diff_kernel<<<((Himg - 2) * (Wimg / 4) + 255) / 256, 256>>>(tgt);
    wmap_kernel<<<HW / 256, 256>>>();
    main_kernel<<<NBLK, NTHR>>>(in, tgt, out);
}